// round 15
// baseline (speedup 1.0000x reference)
#include <cuda_runtime.h>
#include <cstdint>

#define N_NODES 20000
#define FMD 128
#define NH 8
#define OCD 128
#define N_EDGE 160000
#define ETOT 180000           /* E + self loops */
#define CIRCN 504
#define MIRN 19496            /* N - CIRC */
#define PQ 9825984            /* CIRC * MIRN */
#define HCOLS 1024            /* H * FM */

#define BN 128
#define BK 32
#define SAST 36               /* sA row stride (floats): conflict-free */
#define SBST 136              /* sB k-row stride (floats): conflict-free */
#define SCAN_BLK ((N_NODES + 1023) / 1024)   /* 20 */

// ---------------- side stream for fork-join overlap (created pre-main) -----
static cudaStream_t g_s1;
static cudaEvent_t  g_evF, g_evJ;
struct _StreamInit {
    _StreamInit() {
        cudaStreamCreateWithFlags(&g_s1, cudaStreamNonBlocking);
        cudaEventCreateWithFlags(&g_evF, cudaEventDisableTiming);
        cudaEventCreateWithFlags(&g_evJ, cudaEventDisableTiming);
    }
};
static _StreamInit _stream_init;

// ---------------- scratch (device globals; no runtime allocation) ----------
__device__ float    g_h[(size_t)N_NODES * HCOLS];   // y buffer
__device__ float    g_s[N_NODES * NH];
__device__ float    g_d[N_NODES * NH];
__device__ int      g_deg[N_NODES];
__device__ int      g_off[N_NODES + 1];
__device__ int      g_cur[N_NODES];
__device__ int      g_bsum[SCAN_BLK];
__device__ int      g_srcS[ETOT];
__device__ int      g_srcC[ETOT];
__device__ int      g_dstC[ETOT];
__device__ int      g_is64;
__device__ float    g_x1[N_NODES * FMD];
__device__ float    g_x2[N_NODES * FMD];
__device__ float    g_As[FMD * NH];
__device__ float    g_Ad[FMD * NH];

// fp32 -> tf32 (round to nearest)
__device__ __forceinline__ unsigned f2tf(float f) {
    unsigned r;
    asm("cvt.rna.tf32.f32 %0, %1;" : "=r"(r) : "f"(f));
    return r;
}

// m16n8k8 tf32 MMA, fp32 accumulate
__device__ __forceinline__ void mma_tf32(float* d, const unsigned* a, const unsigned* b) {
    asm("mma.sync.aligned.m16n8k8.row.col.f32.tf32.tf32.f32 "
        "{%0,%1,%2,%3}, {%4,%5,%6,%7}, {%8,%9}, {%0,%1,%2,%3};"
        : "+f"(d[0]), "+f"(d[1]), "+f"(d[2]), "+f"(d[3])
        : "r"(a[0]), "r"(a[1]), "r"(a[2]), "r"(a[3]), "r"(b[0]), "r"(b[1]));
}

// ---------------- CSR build ------------------------------------------------
__global__ void k_init(const int* __restrict__ ei32) {
    int i = blockIdx.x * 256 + threadIdx.x;
    if (i < N_NODES) g_deg[i] = 0;
    if (i == 0) {
        int allz = 1;
        #pragma unroll
        for (int j = 1; j < 32; j += 2)
            if (ei32[j] != 0) allz = 0;
        g_is64 = allz;
    }
}

__global__ void k_decode(const void* __restrict__ ei) {
    int i = blockIdx.x * 256 + threadIdx.x;
    if (i >= ETOT) return;
    int src, dst;
    if (i < N_EDGE) {
        if (g_is64) {
            const long long* p = (const long long*)ei;
            src = (int)p[i];
            dst = (int)p[N_EDGE + i];
        } else {
            const int* p = (const int*)ei;
            src = p[i];
            dst = p[N_EDGE + i];
        }
    } else {
        src = dst = i - N_EDGE;
    }
    g_srcC[i] = src;
    g_dstC[i] = dst;
    atomicAdd(&g_deg[dst], 1);
}

__global__ void __launch_bounds__(1024) k_scan1() {
    __shared__ int wsum[32];
    int t = threadIdx.x, lane = t & 31, wid = t >> 5;
    int i = blockIdx.x * 1024 + t;
    int v0 = (i < N_NODES) ? g_deg[i] : 0;
    int v = v0;
    #pragma unroll
    for (int o = 1; o < 32; o <<= 1) {
        int u = __shfl_up_sync(0xffffffffu, v, o);
        if (lane >= o) v += u;
    }
    if (lane == 31) wsum[wid] = v;
    __syncthreads();
    if (wid == 0) {
        int w = wsum[lane];
        #pragma unroll
        for (int o = 1; o < 32; o <<= 1) {
            int u = __shfl_up_sync(0xffffffffu, w, o);
            if (lane >= o) w += u;
        }
        wsum[lane] = w;
    }
    __syncthreads();
    int incl = v + (wid ? wsum[wid - 1] : 0);
    if (i < N_NODES) g_cur[i] = incl;
    if (t == 1023) g_bsum[blockIdx.x] = incl;
}

__global__ void __launch_bounds__(1024) k_scan3() {
    __shared__ int boff[32];
    int t = threadIdx.x;
    if (t < 32) {
        int s = (t < SCAN_BLK) ? g_bsum[t] : 0;
        int v = s;
        #pragma unroll
        for (int o = 1; o < 32; o <<= 1) {
            int u = __shfl_up_sync(0xffffffffu, v, o);
            if (t >= o) v += u;
        }
        boff[t] = v - s;
        if (t == SCAN_BLK - 1 && blockIdx.x == 0) g_off[N_NODES] = v;
    }
    __syncthreads();
    int i = blockIdx.x * 1024 + t;
    if (i < N_NODES) {
        int excl = boff[blockIdx.x] + g_cur[i] - g_deg[i];
        g_off[i] = excl;
        g_cur[i] = excl;
    }
}

__global__ void k_scatter() {
    int i = blockIdx.x * 256 + threadIdx.x;
    if (i >= ETOT) return;
    int pos = atomicAdd(&g_cur[g_dstC[i]], 1);
    g_srcS[pos] = g_srcC[i];
}

// ---------------- folded attention -----------------------------------------
__global__ void __launch_bounds__(128) k_fold(
    const float* __restrict__ W,
    const float* __restrict__ as, const float* __restrict__ ad)
{
    int kh = blockIdx.x;
    int k = kh >> 3, h = kh & 7;
    int t = threadIdx.x;
    float wv = W[(size_t)k * HCOLS + h * FMD + t];
    float sa = wv * as[h * FMD + t];
    float sd = wv * ad[h * FMD + t];
    __shared__ float sh[8];
    int lane = t & 31, wid = t >> 5;
    #pragma unroll
    for (int o = 16; o; o >>= 1) {
        sa += __shfl_xor_sync(0xffffffffu, sa, o);
        sd += __shfl_xor_sync(0xffffffffu, sd, o);
    }
    if (lane == 0) { sh[wid] = sa; sh[4 + wid] = sd; }
    __syncthreads();
    if (t == 0) {
        g_As[k * NH + h] = sh[0] + sh[1] + sh[2] + sh[3];
        g_Ad[k * NH + h] = sh[4] + sh[5] + sh[6] + sh[7];
    }
}

// ---------------- s,d = x @ As / x @ Ad ------------------------------------
__global__ void __launch_bounds__(512) k_sd2(const float* __restrict__ Xext, int xsel) {
    const float* X = (xsel == 1) ? g_x1 : Xext;
    int n = blockIdx.x * 8 + (threadIdx.x >> 6);
    if (n >= N_NODES) return;
    int w = (threadIdx.x >> 5) & 1, lane = threadIdx.x & 31;
    const float* xr = X + (size_t)n * FMD;
    const float* Av = (w == 0) ? g_As : g_Ad;
    float part[NH] = {};
    #pragma unroll
    for (int kk = 0; kk < 4; kk++) {
        int k = lane + kk * 32;
        float xv = xr[k];
        #pragma unroll
        for (int h = 0; h < NH; h++)
            part[h] += xv * Av[k * NH + h];
    }
    #pragma unroll
    for (int h = 0; h < NH; h++) {
        float v = part[h];
        #pragma unroll
        for (int o = 16; o; o >>= 1)
            v += __shfl_xor_sync(0xffffffffu, v, o);
        part[h] = v;
    }
    if (lane == 0) {
        float* o = (w == 0) ? g_s : g_d;
        #pragma unroll
        for (int h = 0; h < NH; h++) o[n * NH + h] = part[h];
    }
}

// ---------------- fused softmax + aggregation (warp per node) --------------
// Edge-batched: 8 independent gathers in flight before the dependent math.
__global__ void __launch_bounds__(128) k_attagg(const float* __restrict__ Xext, int xsel) {
    const float* X = (xsel == 1) ? g_x1 : Xext;
    int warp = threadIdx.x >> 5, lane = threadIdx.x & 31;
    int n = blockIdx.x * 4 + warp;
    if (n >= N_NODES) return;
    int e0 = g_off[n], e1 = g_off[n + 1];

    float dn = (lane < 8) ? g_d[n * NH + lane] : 0.f;

    // pass 1: online softmax max/denominator, batched loads
    float m = -1e30f, den = 0.f;
    for (int j = e0; j < e1; j += 8) {
        int cnt = e1 - j; if (cnt > 8) cnt = 8;
        float vs[8];
        #pragma unroll
        for (int c = 0; c < 8; c++) {
            if (c < cnt) {
                int s = g_srcS[j + c];
                vs[c] = (lane < 8) ? g_s[s * NH + lane] : 0.f;
            }
        }
        if (lane < 8) {
            #pragma unroll
            for (int c = 0; c < 8; c++) {
                if (c < cnt) {
                    float v = vs[c] + dn;
                    v = (v > 0.f) ? v : 0.2f * v;
                    float mn = fmaxf(m, v);
                    den = den * __expf(m - mn) + __expf(v - mn);
                    m = mn;
                }
            }
        }
    }
    float inv = 1.f / (den + 1e-16f);

    // pass 2: alpha-weighted gather, batched X-row prefetch
    float4 acc[NH];
    #pragma unroll
    for (int h = 0; h < NH; h++) acc[h] = make_float4(0.f, 0.f, 0.f, 0.f);

    for (int j = e0; j < e1; j += 8) {
        int cnt = e1 - j; if (cnt > 8) cnt = 8;
        int ss[8];
        #pragma unroll
        for (int c = 0; c < 8; c++)
            if (c < cnt) ss[c] = g_srcS[j + c];
        float4 xs[8];
        #pragma unroll
        for (int c = 0; c < 8; c++)
            if (c < cnt) xs[c] = *(const float4*)(X + (size_t)ss[c] * FMD + lane * 4);
        float als[8];
        #pragma unroll
        for (int c = 0; c < 8; c++) {
            if (c < cnt) {
                float al = 0.f;
                if (lane < 8) {
                    float v = g_s[ss[c] * NH + lane] + dn;
                    v = (v > 0.f) ? v : 0.2f * v;
                    al = __expf(v - m) * inv;
                }
                als[c] = al;
            }
        }
        #pragma unroll
        for (int c = 0; c < 8; c++) {
            if (c < cnt) {
                #pragma unroll
                for (int h = 0; h < NH; h++) {
                    float a = __shfl_sync(0xffffffffu, als[c], h);
                    acc[h].x += a * xs[c].x;
                    acc[h].y += a * xs[c].y;
                    acc[h].z += a * xs[c].z;
                    acc[h].w += a * xs[c].w;
                }
            }
        }
    }
    float* yr = g_h + (size_t)n * HCOLS + lane * 4;
    #pragma unroll
    for (int h = 0; h < NH; h++)
        *(float4*)(yr + h * FMD) = acc[h];
}

// ---------------- tf32 tensor-core GEMM (synchronous, occupancy-tiled) -----
// C[M,Nn] = A[M,K] * B'[K,Nn]   (fp32 accumulate, tf32 operands)
// TBM  : 128 (P-GEMM) or 64 (Nn=128 GEMMs)
// ASEL : 0 = ext A, 1 = g_h, 2 = dual [g_x1 | g_x2] along K (stride 128 each)
// BMODE: 0 = NT (B is [Nn,K] row-major) ; 1 = W-permuted NN (Nn==128)
// MODE : 0 = plain ; 1 = +bias route circ/mir ; 2 = relu(v*0.125+bias)->g_x1/g_x2
template <int TBM, int ASEL, int BMODE, int MODE>
__global__ void __launch_bounds__(256, (TBM == 64) ? 3 : 2) gemm_tc(
    const float* __restrict__ A, const float* __restrict__ B,
    const float* __restrict__ bias, float* __restrict__ C,
    int M, int Nn, int K, int osel)
{
    constexpr int MT = TBM / 32;          // m16 tiles per warp
    __shared__ unsigned sA[TBM * SAST];
    __shared__ unsigned sB[BK * SBST];

    int tid  = threadIdx.x;
    int lane = tid & 31;
    int w    = tid >> 5;
    int warp_m = w & 1;
    int warp_n = w >> 1;
    int m0 = blockIdx.x * TBM, n0 = blockIdx.y * BN;

    const float* Ap = (ASEL == 1) ? g_h : A;

    float acc[MT][4][4];
    #pragma unroll
    for (int i = 0; i < MT; i++)
        #pragma unroll
        for (int j = 0; j < 4; j++)
            #pragma unroll
            for (int q = 0; q < 4; q++) acc[i][j][q] = 0.f;

    for (int kc = 0; kc < K; kc += BK) {
        #pragma unroll
        for (int p = 0; p < TBM / 32; p++) {
            int r = (tid >> 3) + p * 32;
            int q = (tid & 7) * 4;
            float4 v = make_float4(0.f, 0.f, 0.f, 0.f);
            int m = m0 + r;
            if (m < M) {
                if (ASEL == 2) {
                    int kg = kc + q;
                    const float* src = (kg < FMD)
                        ? (g_x1 + (size_t)m * FMD + kg)
                        : (g_x2 + (size_t)m * FMD + (kg - FMD));
                    v = *(const float4*)src;
                } else {
                    v = *(const float4*)(Ap + (size_t)m * K + kc + q);
                }
            }
            unsigned* dst = &sA[r * SAST + q];
            dst[0] = f2tf(v.x); dst[1] = f2tf(v.y);
            dst[2] = f2tf(v.z); dst[3] = f2tf(v.w);
        }
        if (BMODE == 1) {
            #pragma unroll
            for (int p = 0; p < 4; p++) {
                int kk = (tid >> 5) + p * 8;
                int c  = (tid & 31) * 4;
                int gk = kc + kk;
                float4 v = *(const float4*)(B + (size_t)(gk & 127) * HCOLS
                                              + ((gk >> 7) << 7) + c);
                unsigned* dst = &sB[kk * SBST + c];
                dst[0] = f2tf(v.x); dst[1] = f2tf(v.y);
                dst[2] = f2tf(v.z); dst[3] = f2tf(v.w);
            }
        } else {
            #pragma unroll
            for (int p = 0; p < 4; p++) {
                int n = (tid >> 3) + p * 32;
                int q = (tid & 7) * 4;
                float4 v = make_float4(0.f, 0.f, 0.f, 0.f);
                if (n0 + n < Nn)
                    v = *(const float4*)(B + (size_t)(n0 + n) * K + kc + q);
                sB[(q + 0) * SBST + n] = f2tf(v.x);
                sB[(q + 1) * SBST + n] = f2tf(v.y);
                sB[(q + 2) * SBST + n] = f2tf(v.z);
                sB[(q + 3) * SBST + n] = f2tf(v.w);
            }
        }
        __syncthreads();

        #pragma unroll
        for (int k8 = 0; k8 < 4; k8++) {
            int kb = k8 * 8;
            unsigned a[MT][4], b[4][2];
            #pragma unroll
            for (int mt = 0; mt < MT; mt++) {
                int row = warp_m * (TBM / 2) + mt * 16 + (lane >> 2);
                const unsigned* base = &sA[row * SAST + kb + (lane & 3)];
                a[mt][0] = base[0];
                a[mt][1] = base[8 * SAST];
                a[mt][2] = base[4];
                a[mt][3] = base[8 * SAST + 4];
            }
            #pragma unroll
            for (int nt = 0; nt < 4; nt++) {
                int n = warp_n * 32 + nt * 8 + (lane >> 2);
                const unsigned* base = &sB[(kb + (lane & 3)) * SBST + n];
                b[nt][0] = base[0];
                b[nt][1] = base[4 * SBST];
            }
            #pragma unroll
            for (int mt = 0; mt < MT; mt++)
                #pragma unroll
                for (int nt = 0; nt < 4; nt++)
                    mma_tf32(acc[mt][nt], a[mt], b[nt]);
        }
        __syncthreads();
    }

    #pragma unroll
    for (int mt = 0; mt < MT; mt++) {
        int rg = m0 + warp_m * (TBM / 2) + mt * 16 + (lane >> 2);
        #pragma unroll
        for (int nt = 0; nt < 4; nt++) {
            int colg = n0 + warp_n * 32 + nt * 8 + (lane & 3) * 2;
            const float* dv = acc[mt][nt];
            #pragma unroll
            for (int half = 0; half < 2; half++) {
                int m = rg + half * 8;
                if (m >= M) continue;
                float v0 = dv[half * 2 + 0];
                float v1 = dv[half * 2 + 1];
                if (MODE == 0) {
                    if (colg + 1 < Nn) {
                        *(float2*)(C + (size_t)m * Nn + colg) = make_float2(v0, v1);
                    } else if (colg < Nn) {
                        C[(size_t)m * Nn + colg] = v0;
                    }
                } else if (MODE == 1) {
                    v0 += bias[colg];
                    v1 += bias[colg + 1];
                    float* base = (m < CIRCN)
                        ? (C + PQ + (size_t)m * OCD)
                        : (C + PQ + (size_t)CIRCN * OCD + (size_t)(m - CIRCN) * OCD);
                    *(float2*)(base + colg) = make_float2(v0, v1);
                } else {
                    v0 = fmaxf(v0 * 0.125f + bias[colg], 0.f);
                    v1 = fmaxf(v1 * 0.125f + bias[colg + 1], 0.f);
                    float* o = (osel == 1) ? g_x1 : g_x2;
                    *(float2*)(o + (size_t)m * FMD + colg) = make_float2(v0, v1);
                }
            }
        }
    }
}

// ---------------- launch ---------------------------------------------------
extern "C" void kernel_launch(void* const* d_in, const int* in_sizes, int n_in,
                              void* d_out, int out_size)
{
    const float* x   = (const float*)d_in[0];
    const void*  ei  = d_in[1];
    const float* W1  = (const float*)d_in[2];
    const float* as1 = (const float*)d_in[3];
    const float* ad1 = (const float*)d_in[4];
    const float* b1  = (const float*)d_in[5];
    const float* W2  = (const float*)d_in[6];
    const float* as2 = (const float*)d_in[7];
    const float* ad2 = (const float*)d_in[8];
    const float* b2  = (const float*)d_in[9];
    const float* Wc  = (const float*)d_in[10];
    const float* bc  = (const float*)d_in[11];
    float* out = (float*)d_out;

    dim3 gOut64((N_NODES + 63) / 64, 1);     // 313 CTAs
    int gAtt = (N_NODES + 3) / 4;
    int gSd  = (N_NODES + 7) / 8;

    // ---- fork: attention-prep chain on side stream s1 ----
    cudaEventRecord(g_evF, 0);
    cudaStreamWaitEvent(g_s1, g_evF, 0);
    k_fold<<<HCOLS, 128, 0, g_s1>>>(W1, as1, ad1);
    k_sd2<<<gSd, 512, 0, g_s1>>>(x, 0);
    k_fold<<<HCOLS, 128, 0, g_s1>>>(W2, as2, ad2);   // sd2_1 done reading As/Ad
    cudaEventRecord(g_evJ, g_s1);

    // ---- main stream: CSR build ----
    k_init<<<(N_NODES + 255) / 256, 256>>>((const int*)ei);
    k_decode<<<(ETOT + 255) / 256, 256>>>(ei);
    k_scan1<<<SCAN_BLK, 1024>>>();
    k_scan3<<<SCAN_BLK, 1024>>>();
    k_scatter<<<(ETOT + 255) / 256, 256>>>();

    // ---- join: attagg needs CSR + (fold1, sd2_1); sd2_2 needs fold2 ----
    cudaStreamWaitEvent(0, g_evJ, 0);

    // ---- layer 1 ----
    k_attagg<<<gAtt, 128>>>(x, 0);
    gemm_tc<64, 1, 1, 2><<<gOut64, 256>>>(nullptr, W1, b1, nullptr,
                                          N_NODES, FMD, HCOLS, 1);

    // ---- layer 2 ----
    k_sd2<<<gSd, 512>>>(nullptr, 1);
    k_attagg<<<gAtt, 128>>>(nullptr, 1);
    gemm_tc<64, 1, 1, 2><<<gOut64, 256>>>(nullptr, W2, b2, nullptr,
                                          N_NODES, FMD, HCOLS, 2);

    // ---- classifier ----
    gemm_tc<64, 2, 0, 1><<<gOut64, 256>>>(nullptr, Wc, bc, out,
                                          N_NODES, OCD, 2 * FMD, 0);

    // ---- P = circ @ mir^T ----
    const float* circ = out + PQ;
    const float* mir  = out + PQ + (size_t)CIRCN * OCD;
    dim3 gP((CIRCN + 127) / 128, (MIRN + BN - 1) / BN);
    gemm_tc<128, 0, 0, 0><<<gP, 256>>>(circ, mir, nullptr, out,
                                       CIRCN, MIRN, FMD, 0);
}

// round 16
// speedup vs baseline: 1.1069x; 1.1069x over previous
#include <cuda_runtime.h>
#include <cstdint>

#define N_NODES 20000
#define FMD 128
#define NH 8
#define OCD 128
#define N_EDGE 160000
#define ETOT 180000           /* E + self loops */
#define CIRCN 504
#define MIRN 19496            /* N - CIRC */
#define PQ 9825984            /* CIRC * MIRN */
#define HCOLS 1024            /* H * FM */

#define BN 128
#define BK 32
#define SAST 36               /* sA row stride (floats): conflict-free */
#define SBST 136              /* sB k-row stride (floats): conflict-free */
#define SCAN_BLK ((N_NODES + 1023) / 1024)   /* 20 */

// ---------------- side stream for fork-join overlap (created pre-main) -----
static cudaStream_t g_s1;
static cudaEvent_t  g_evF, g_evJ;
struct _StreamInit {
    _StreamInit() {
        cudaStreamCreateWithFlags(&g_s1, cudaStreamNonBlocking);
        cudaEventCreateWithFlags(&g_evF, cudaEventDisableTiming);
        cudaEventCreateWithFlags(&g_evJ, cudaEventDisableTiming);
    }
};
static _StreamInit _stream_init;

// ---------------- scratch (device globals; no runtime allocation) ----------
__device__ float    g_h[(size_t)N_NODES * HCOLS];   // y buffer
__device__ float    g_s[N_NODES * NH];
__device__ float    g_d[N_NODES * NH];
__device__ int      g_deg[N_NODES];
__device__ int      g_off[N_NODES + 1];
__device__ int      g_cur[N_NODES];
__device__ int      g_bsum[SCAN_BLK];
__device__ int      g_srcS[ETOT];
__device__ int      g_srcC[ETOT];
__device__ int      g_dstC[ETOT];
__device__ int      g_is64;
__device__ float    g_x1[N_NODES * FMD];
__device__ float    g_x2[N_NODES * FMD];
__device__ float    g_As[FMD * NH];
__device__ float    g_Ad[FMD * NH];

// fp32 -> tf32 (round to nearest)
__device__ __forceinline__ unsigned f2tf(float f) {
    unsigned r;
    asm("cvt.rna.tf32.f32 %0, %1;" : "=r"(r) : "f"(f));
    return r;
}

// m16n8k8 tf32 MMA, fp32 accumulate
__device__ __forceinline__ void mma_tf32(float* d, const unsigned* a, const unsigned* b) {
    asm("mma.sync.aligned.m16n8k8.row.col.f32.tf32.tf32.f32 "
        "{%0,%1,%2,%3}, {%4,%5,%6,%7}, {%8,%9}, {%0,%1,%2,%3};"
        : "+f"(d[0]), "+f"(d[1]), "+f"(d[2]), "+f"(d[3])
        : "r"(a[0]), "r"(a[1]), "r"(a[2]), "r"(a[3]), "r"(b[0]), "r"(b[1]));
}

// ---------------- CSR build ------------------------------------------------
__global__ void k_init(const int* __restrict__ ei32) {
    int i = blockIdx.x * 256 + threadIdx.x;
    if (i < N_NODES) g_deg[i] = 0;
    if (i == 0) {
        int allz = 1;
        #pragma unroll
        for (int j = 1; j < 32; j += 2)
            if (ei32[j] != 0) allz = 0;
        g_is64 = allz;
    }
}

__global__ void k_decode(const void* __restrict__ ei) {
    int i = blockIdx.x * 256 + threadIdx.x;
    if (i >= ETOT) return;
    int src, dst;
    if (i < N_EDGE) {
        if (g_is64) {
            const long long* p = (const long long*)ei;
            src = (int)p[i];
            dst = (int)p[N_EDGE + i];
        } else {
            const int* p = (const int*)ei;
            src = p[i];
            dst = p[N_EDGE + i];
        }
    } else {
        src = dst = i - N_EDGE;
    }
    g_srcC[i] = src;
    g_dstC[i] = dst;
    atomicAdd(&g_deg[dst], 1);
}

__global__ void __launch_bounds__(1024) k_scan1() {
    __shared__ int wsum[32];
    int t = threadIdx.x, lane = t & 31, wid = t >> 5;
    int i = blockIdx.x * 1024 + t;
    int v0 = (i < N_NODES) ? g_deg[i] : 0;
    int v = v0;
    #pragma unroll
    for (int o = 1; o < 32; o <<= 1) {
        int u = __shfl_up_sync(0xffffffffu, v, o);
        if (lane >= o) v += u;
    }
    if (lane == 31) wsum[wid] = v;
    __syncthreads();
    if (wid == 0) {
        int w = wsum[lane];
        #pragma unroll
        for (int o = 1; o < 32; o <<= 1) {
            int u = __shfl_up_sync(0xffffffffu, w, o);
            if (lane >= o) w += u;
        }
        wsum[lane] = w;
    }
    __syncthreads();
    int incl = v + (wid ? wsum[wid - 1] : 0);
    if (i < N_NODES) g_cur[i] = incl;
    if (t == 1023) g_bsum[blockIdx.x] = incl;
}

__global__ void __launch_bounds__(1024) k_scan3() {
    __shared__ int boff[32];
    int t = threadIdx.x;
    if (t < 32) {
        int s = (t < SCAN_BLK) ? g_bsum[t] : 0;
        int v = s;
        #pragma unroll
        for (int o = 1; o < 32; o <<= 1) {
            int u = __shfl_up_sync(0xffffffffu, v, o);
            if (t >= o) v += u;
        }
        boff[t] = v - s;
        if (t == SCAN_BLK - 1 && blockIdx.x == 0) g_off[N_NODES] = v;
    }
    __syncthreads();
    int i = blockIdx.x * 1024 + t;
    if (i < N_NODES) {
        int excl = boff[blockIdx.x] + g_cur[i] - g_deg[i];
        g_off[i] = excl;
        g_cur[i] = excl;
    }
}

__global__ void k_scatter() {
    int i = blockIdx.x * 256 + threadIdx.x;
    if (i >= ETOT) return;
    int pos = atomicAdd(&g_cur[g_dstC[i]], 1);
    g_srcS[pos] = g_srcC[i];
}

// ---------------- folded attention -----------------------------------------
__global__ void __launch_bounds__(128) k_fold(
    const float* __restrict__ W,
    const float* __restrict__ as, const float* __restrict__ ad)
{
    int kh = blockIdx.x;
    int k = kh >> 3, h = kh & 7;
    int t = threadIdx.x;
    float wv = W[(size_t)k * HCOLS + h * FMD + t];
    float sa = wv * as[h * FMD + t];
    float sd = wv * ad[h * FMD + t];
    __shared__ float sh[8];
    int lane = t & 31, wid = t >> 5;
    #pragma unroll
    for (int o = 16; o; o >>= 1) {
        sa += __shfl_xor_sync(0xffffffffu, sa, o);
        sd += __shfl_xor_sync(0xffffffffu, sd, o);
    }
    if (lane == 0) { sh[wid] = sa; sh[4 + wid] = sd; }
    __syncthreads();
    if (t == 0) {
        g_As[k * NH + h] = sh[0] + sh[1] + sh[2] + sh[3];
        g_Ad[k * NH + h] = sh[4] + sh[5] + sh[6] + sh[7];
    }
}

// ---------------- s,d = x @ As / x @ Ad ------------------------------------
__global__ void __launch_bounds__(512) k_sd2(const float* __restrict__ Xext, int xsel) {
    const float* X = (xsel == 1) ? g_x1 : Xext;
    int n = blockIdx.x * 8 + (threadIdx.x >> 6);
    if (n >= N_NODES) return;
    int w = (threadIdx.x >> 5) & 1, lane = threadIdx.x & 31;
    const float* xr = X + (size_t)n * FMD;
    const float* Av = (w == 0) ? g_As : g_Ad;
    float part[NH] = {};
    #pragma unroll
    for (int kk = 0; kk < 4; kk++) {
        int k = lane + kk * 32;
        float xv = xr[k];
        #pragma unroll
        for (int h = 0; h < NH; h++)
            part[h] += xv * Av[k * NH + h];
    }
    #pragma unroll
    for (int h = 0; h < NH; h++) {
        float v = part[h];
        #pragma unroll
        for (int o = 16; o; o >>= 1)
            v += __shfl_xor_sync(0xffffffffu, v, o);
        part[h] = v;
    }
    if (lane == 0) {
        float* o = (w == 0) ? g_s : g_d;
        #pragma unroll
        for (int h = 0; h < NH; h++) o[n * NH + h] = part[h];
    }
}

// ---------------- fused softmax + aggregation (warp per node) --------------
// Depth-2 software pipeline on the edge loop (low register cost).
__global__ void __launch_bounds__(128) k_attagg(const float* __restrict__ Xext, int xsel) {
    const float* X = (xsel == 1) ? g_x1 : Xext;
    int warp = threadIdx.x >> 5, lane = threadIdx.x & 31;
    int n = blockIdx.x * 4 + warp;
    if (n >= N_NODES) return;
    int e0 = g_off[n], e1 = g_off[n + 1];   // e1 > e0 always (self loop)

    float dn = (lane < 8) ? g_d[n * NH + lane] : 0.f;

    // pass 1: online softmax max/denominator (depth-2 prefetch of g_s)
    float m = -1e30f, den = 0.f;
    {
        int s_cur = g_srcS[e0];
        float sv = (lane < 8) ? g_s[s_cur * NH + lane] : 0.f;
        for (int j = e0; j < e1; j++) {
            float sn = sv;
            if (j + 1 < e1) {
                int s_nx = g_srcS[j + 1];
                sn = (lane < 8) ? g_s[s_nx * NH + lane] : 0.f;
            }
            if (lane < 8) {
                float v = sv + dn;
                v = (v > 0.f) ? v : 0.2f * v;
                float mn = fmaxf(m, v);
                den = den * __expf(m - mn) + __expf(v - mn);
                m = mn;
            }
            sv = sn;
        }
    }
    float inv = 1.f / (den + 1e-16f);

    // pass 2: alpha-weighted gather (depth-2 prefetch of src, X row, g_s)
    float4 acc[NH];
    #pragma unroll
    for (int h = 0; h < NH; h++) acc[h] = make_float4(0.f, 0.f, 0.f, 0.f);

    {
        int s_cur = g_srcS[e0];
        float4 xv = *(const float4*)(X + (size_t)s_cur * FMD + lane * 4);
        float sv = (lane < 8) ? g_s[s_cur * NH + lane] : 0.f;
        for (int j = e0; j < e1; j++) {
            float4 xn = xv;
            float sn = sv;
            if (j + 1 < e1) {
                int s_nx = g_srcS[j + 1];
                xn = *(const float4*)(X + (size_t)s_nx * FMD + lane * 4);
                sn = (lane < 8) ? g_s[s_nx * NH + lane] : 0.f;
            }
            float al = 0.f;
            if (lane < 8) {
                float v = sv + dn;
                v = (v > 0.f) ? v : 0.2f * v;
                al = __expf(v - m) * inv;
            }
            #pragma unroll
            for (int h = 0; h < NH; h++) {
                float a = __shfl_sync(0xffffffffu, al, h);
                acc[h].x += a * xv.x;
                acc[h].y += a * xv.y;
                acc[h].z += a * xv.z;
                acc[h].w += a * xv.w;
            }
            xv = xn;
            sv = sn;
        }
    }
    float* yr = g_h + (size_t)n * HCOLS + lane * 4;
    #pragma unroll
    for (int h = 0; h < NH; h++)
        *(float4*)(yr + h * FMD) = acc[h];
}

// ---------------- tf32 tensor-core GEMM (synchronous, occupancy-tiled) -----
// C[M,Nn] = A[M,K] * B'[K,Nn]   (fp32 accumulate, tf32 operands)
// TBM  : 128 (P-GEMM) or 64 (Nn=128 GEMMs)
// ASEL : 0 = ext A, 1 = g_h, 2 = dual [g_x1 | g_x2] along K (stride 128 each)
// BMODE: 0 = NT (B is [Nn,K] row-major) ; 1 = W-permuted NN (Nn==128)
// MODE : 0 = plain ; 1 = +bias route circ/mir ; 2 = relu(v*0.125+bias)->g_x1/g_x2
template <int TBM, int ASEL, int BMODE, int MODE>
__global__ void __launch_bounds__(256, (TBM == 64) ? 3 : 2) gemm_tc(
    const float* __restrict__ A, const float* __restrict__ B,
    const float* __restrict__ bias, float* __restrict__ C,
    int M, int Nn, int K, int osel)
{
    constexpr int MT = TBM / 32;          // m16 tiles per warp
    __shared__ unsigned sA[TBM * SAST];
    __shared__ unsigned sB[BK * SBST];

    int tid  = threadIdx.x;
    int lane = tid & 31;
    int w    = tid >> 5;
    int warp_m = w & 1;
    int warp_n = w >> 1;
    int m0 = blockIdx.x * TBM, n0 = blockIdx.y * BN;

    const float* Ap = (ASEL == 1) ? g_h : A;

    float acc[MT][4][4];
    #pragma unroll
    for (int i = 0; i < MT; i++)
        #pragma unroll
        for (int j = 0; j < 4; j++)
            #pragma unroll
            for (int q = 0; q < 4; q++) acc[i][j][q] = 0.f;

    for (int kc = 0; kc < K; kc += BK) {
        #pragma unroll
        for (int p = 0; p < TBM / 32; p++) {
            int r = (tid >> 3) + p * 32;
            int q = (tid & 7) * 4;
            float4 v = make_float4(0.f, 0.f, 0.f, 0.f);
            int m = m0 + r;
            if (m < M) {
                if (ASEL == 2) {
                    int kg = kc + q;
                    const float* src = (kg < FMD)
                        ? (g_x1 + (size_t)m * FMD + kg)
                        : (g_x2 + (size_t)m * FMD + (kg - FMD));
                    v = *(const float4*)src;
                } else {
                    v = *(const float4*)(Ap + (size_t)m * K + kc + q);
                }
            }
            unsigned* dst = &sA[r * SAST + q];
            dst[0] = f2tf(v.x); dst[1] = f2tf(v.y);
            dst[2] = f2tf(v.z); dst[3] = f2tf(v.w);
        }
        if (BMODE == 1) {
            #pragma unroll
            for (int p = 0; p < 4; p++) {
                int kk = (tid >> 5) + p * 8;
                int c  = (tid & 31) * 4;
                int gk = kc + kk;
                float4 v = *(const float4*)(B + (size_t)(gk & 127) * HCOLS
                                              + ((gk >> 7) << 7) + c);
                unsigned* dst = &sB[kk * SBST + c];
                dst[0] = f2tf(v.x); dst[1] = f2tf(v.y);
                dst[2] = f2tf(v.z); dst[3] = f2tf(v.w);
            }
        } else {
            #pragma unroll
            for (int p = 0; p < 4; p++) {
                int n = (tid >> 3) + p * 32;
                int q = (tid & 7) * 4;
                float4 v = make_float4(0.f, 0.f, 0.f, 0.f);
                if (n0 + n < Nn)
                    v = *(const float4*)(B + (size_t)(n0 + n) * K + kc + q);
                sB[(q + 0) * SBST + n] = f2tf(v.x);
                sB[(q + 1) * SBST + n] = f2tf(v.y);
                sB[(q + 2) * SBST + n] = f2tf(v.z);
                sB[(q + 3) * SBST + n] = f2tf(v.w);
            }
        }
        __syncthreads();

        #pragma unroll
        for (int k8 = 0; k8 < 4; k8++) {
            int kb = k8 * 8;
            unsigned a[MT][4], b[4][2];
            #pragma unroll
            for (int mt = 0; mt < MT; mt++) {
                int row = warp_m * (TBM / 2) + mt * 16 + (lane >> 2);
                const unsigned* base = &sA[row * SAST + kb + (lane & 3)];
                a[mt][0] = base[0];
                a[mt][1] = base[8 * SAST];
                a[mt][2] = base[4];
                a[mt][3] = base[8 * SAST + 4];
            }
            #pragma unroll
            for (int nt = 0; nt < 4; nt++) {
                int n = warp_n * 32 + nt * 8 + (lane >> 2);
                const unsigned* base = &sB[(kb + (lane & 3)) * SBST + n];
                b[nt][0] = base[0];
                b[nt][1] = base[4 * SBST];
            }
            #pragma unroll
            for (int mt = 0; mt < MT; mt++)
                #pragma unroll
                for (int nt = 0; nt < 4; nt++)
                    mma_tf32(acc[mt][nt], a[mt], b[nt]);
        }
        __syncthreads();
    }

    #pragma unroll
    for (int mt = 0; mt < MT; mt++) {
        int rg = m0 + warp_m * (TBM / 2) + mt * 16 + (lane >> 2);
        #pragma unroll
        for (int nt = 0; nt < 4; nt++) {
            int colg = n0 + warp_n * 32 + nt * 8 + (lane & 3) * 2;
            const float* dv = acc[mt][nt];
            #pragma unroll
            for (int half = 0; half < 2; half++) {
                int m = rg + half * 8;
                if (m >= M) continue;
                float v0 = dv[half * 2 + 0];
                float v1 = dv[half * 2 + 1];
                if (MODE == 0) {
                    if (colg + 1 < Nn) {
                        *(float2*)(C + (size_t)m * Nn + colg) = make_float2(v0, v1);
                    } else if (colg < Nn) {
                        C[(size_t)m * Nn + colg] = v0;
                    }
                } else if (MODE == 1) {
                    v0 += bias[colg];
                    v1 += bias[colg + 1];
                    float* base = (m < CIRCN)
                        ? (C + PQ + (size_t)m * OCD)
                        : (C + PQ + (size_t)CIRCN * OCD + (size_t)(m - CIRCN) * OCD);
                    *(float2*)(base + colg) = make_float2(v0, v1);
                } else {
                    v0 = fmaxf(v0 * 0.125f + bias[colg], 0.f);
                    v1 = fmaxf(v1 * 0.125f + bias[colg + 1], 0.f);
                    float* o = (osel == 1) ? g_x1 : g_x2;
                    *(float2*)(o + (size_t)m * FMD + colg) = make_float2(v0, v1);
                }
            }
        }
    }
}

// ---------------- launch ---------------------------------------------------
extern "C" void kernel_launch(void* const* d_in, const int* in_sizes, int n_in,
                              void* d_out, int out_size)
{
    const float* x   = (const float*)d_in[0];
    const void*  ei  = d_in[1];
    const float* W1  = (const float*)d_in[2];
    const float* as1 = (const float*)d_in[3];
    const float* ad1 = (const float*)d_in[4];
    const float* b1  = (const float*)d_in[5];
    const float* W2  = (const float*)d_in[6];
    const float* as2 = (const float*)d_in[7];
    const float* ad2 = (const float*)d_in[8];
    const float* b2  = (const float*)d_in[9];
    const float* Wc  = (const float*)d_in[10];
    const float* bc  = (const float*)d_in[11];
    float* out = (float*)d_out;

    dim3 gOut64((N_NODES + 63) / 64, 1);     // 313 CTAs
    int gAtt = (N_NODES + 3) / 4;
    int gSd  = (N_NODES + 7) / 8;

    // ---- fork: attention-prep chain on side stream s1 ----
    cudaEventRecord(g_evF, 0);
    cudaStreamWaitEvent(g_s1, g_evF, 0);
    k_fold<<<HCOLS, 128, 0, g_s1>>>(W1, as1, ad1);
    k_sd2<<<gSd, 512, 0, g_s1>>>(x, 0);
    k_fold<<<HCOLS, 128, 0, g_s1>>>(W2, as2, ad2);   // sd2_1 done reading As/Ad
    cudaEventRecord(g_evJ, g_s1);

    // ---- main stream: CSR build ----
    k_init<<<(N_NODES + 255) / 256, 256>>>((const int*)ei);
    k_decode<<<(ETOT + 255) / 256, 256>>>(ei);
    k_scan1<<<SCAN_BLK, 1024>>>();
    k_scan3<<<SCAN_BLK, 1024>>>();
    k_scatter<<<(ETOT + 255) / 256, 256>>>();

    // ---- join: attagg needs CSR + (fold1, sd2_1); sd2_2 needs fold2 ----
    cudaStreamWaitEvent(0, g_evJ, 0);

    // ---- layer 1 ----
    k_attagg<<<gAtt, 128>>>(x, 0);
    gemm_tc<64, 1, 1, 2><<<gOut64, 256>>>(nullptr, W1, b1, nullptr,
                                          N_NODES, FMD, HCOLS, 1);

    // ---- layer 2 ----
    k_sd2<<<gSd, 512>>>(nullptr, 1);
    k_attagg<<<gAtt, 128>>>(nullptr, 1);
    gemm_tc<64, 1, 1, 2><<<gOut64, 256>>>(nullptr, W2, b2, nullptr,
                                          N_NODES, FMD, HCOLS, 2);

    // ---- classifier ----
    gemm_tc<64, 2, 0, 1><<<gOut64, 256>>>(nullptr, Wc, bc, out,
                                          N_NODES, OCD, 2 * FMD, 0);

    // ---- P = circ @ mir^T ----
    const float* circ = out + PQ;
    const float* mir  = out + PQ + (size_t)CIRCN * OCD;
    dim3 gP((CIRCN + 127) / 128, (MIRN + BN - 1) / BN);
    gemm_tc<128, 0, 0, 0><<<gP, 256>>>(circ, mir, nullptr, out,
                                       CIRCN, MIRN, FMD, 0);
}

// round 17
// speedup vs baseline: 1.3722x; 1.2397x over previous
#include <cuda_runtime.h>
#include <cuda_fp16.h>
#include <cstdint>

#define N_NODES 20000
#define FMD 128
#define NH 8
#define OCD 128
#define N_EDGE 160000
#define ETOT 180000           /* E + self loops */
#define CIRCN 504
#define MIRN 19496            /* N - CIRC */
#define PQ 9825984            /* CIRC * MIRN */
#define HCOLS 1024            /* H * FM */

#define BN 128
#define BK 32
#define SH 40                 /* smem row stride in halves: conflict-free */
#define SCAN_BLK ((N_NODES + 1023) / 1024)   /* 20 */

// ---------------- side stream for fork-join overlap (created pre-main) -----
static cudaStream_t g_s1;
static cudaEvent_t  g_evF, g_evJ;
struct _StreamInit {
    _StreamInit() {
        cudaStreamCreateWithFlags(&g_s1, cudaStreamNonBlocking);
        cudaEventCreateWithFlags(&g_evF, cudaEventDisableTiming);
        cudaEventCreateWithFlags(&g_evJ, cudaEventDisableTiming);
    }
};
static _StreamInit _stream_init;

// ---------------- scratch (device globals; no runtime allocation) ----------
__device__ float    g_h[(size_t)N_NODES * HCOLS];   // y buffer
__device__ float    g_s[N_NODES * NH];
__device__ float    g_d[N_NODES * NH];
__device__ int      g_deg[N_NODES];
__device__ int      g_off[N_NODES + 1];
__device__ int      g_cur[N_NODES];
__device__ int      g_bsum[SCAN_BLK];
__device__ int      g_srcS[ETOT];
__device__ int      g_srcC[ETOT];
__device__ int      g_dstC[ETOT];
__device__ int      g_is64;
__device__ float    g_x1[N_NODES * FMD];
__device__ float    g_x2[N_NODES * FMD];
__device__ float    g_As[FMD * NH];
__device__ float    g_Ad[FMD * NH];

// m16n8k16 fp16 MMA, fp32 accumulate
__device__ __forceinline__ void mma_f16(float* d, const unsigned* a, const unsigned* b) {
    asm("mma.sync.aligned.m16n8k16.row.col.f32.f16.f16.f32 "
        "{%0,%1,%2,%3}, {%4,%5,%6,%7}, {%8,%9}, {%0,%1,%2,%3};"
        : "+f"(d[0]), "+f"(d[1]), "+f"(d[2]), "+f"(d[3])
        : "r"(a[0]), "r"(a[1]), "r"(a[2]), "r"(a[3]), "r"(b[0]), "r"(b[1]));
}

// ---------------- CSR build ------------------------------------------------
__global__ void k_init(const int* __restrict__ ei32) {
    int i = blockIdx.x * 256 + threadIdx.x;
    if (i < N_NODES) g_deg[i] = 0;
    if (i == 0) {
        int allz = 1;
        #pragma unroll
        for (int j = 1; j < 32; j += 2)
            if (ei32[j] != 0) allz = 0;
        g_is64 = allz;
    }
}

__global__ void k_decode(const void* __restrict__ ei) {
    int i = blockIdx.x * 256 + threadIdx.x;
    if (i >= ETOT) return;
    int src, dst;
    if (i < N_EDGE) {
        if (g_is64) {
            const long long* p = (const long long*)ei;
            src = (int)p[i];
            dst = (int)p[N_EDGE + i];
        } else {
            const int* p = (const int*)ei;
            src = p[i];
            dst = p[N_EDGE + i];
        }
    } else {
        src = dst = i - N_EDGE;
    }
    g_srcC[i] = src;
    g_dstC[i] = dst;
    atomicAdd(&g_deg[dst], 1);
}

__global__ void __launch_bounds__(1024) k_scan1() {
    __shared__ int wsum[32];
    int t = threadIdx.x, lane = t & 31, wid = t >> 5;
    int i = blockIdx.x * 1024 + t;
    int v0 = (i < N_NODES) ? g_deg[i] : 0;
    int v = v0;
    #pragma unroll
    for (int o = 1; o < 32; o <<= 1) {
        int u = __shfl_up_sync(0xffffffffu, v, o);
        if (lane >= o) v += u;
    }
    if (lane == 31) wsum[wid] = v;
    __syncthreads();
    if (wid == 0) {
        int w = wsum[lane];
        #pragma unroll
        for (int o = 1; o < 32; o <<= 1) {
            int u = __shfl_up_sync(0xffffffffu, w, o);
            if (lane >= o) w += u;
        }
        wsum[lane] = w;
    }
    __syncthreads();
    int incl = v + (wid ? wsum[wid - 1] : 0);
    if (i < N_NODES) g_cur[i] = incl;
    if (t == 1023) g_bsum[blockIdx.x] = incl;
}

__global__ void __launch_bounds__(1024) k_scan3() {
    __shared__ int boff[32];
    int t = threadIdx.x;
    if (t < 32) {
        int s = (t < SCAN_BLK) ? g_bsum[t] : 0;
        int v = s;
        #pragma unroll
        for (int o = 1; o < 32; o <<= 1) {
            int u = __shfl_up_sync(0xffffffffu, v, o);
            if (t >= o) v += u;
        }
        boff[t] = v - s;
        if (t == SCAN_BLK - 1 && blockIdx.x == 0) g_off[N_NODES] = v;
    }
    __syncthreads();
    int i = blockIdx.x * 1024 + t;
    if (i < N_NODES) {
        int excl = boff[blockIdx.x] + g_cur[i] - g_deg[i];
        g_off[i] = excl;
        g_cur[i] = excl;
    }
}

__global__ void k_scatter() {
    int i = blockIdx.x * 256 + threadIdx.x;
    if (i >= ETOT) return;
    int pos = atomicAdd(&g_cur[g_dstC[i]], 1);
    g_srcS[pos] = g_srcC[i];
}

// ---------------- folded attention -----------------------------------------
__global__ void __launch_bounds__(128) k_fold(
    const float* __restrict__ W,
    const float* __restrict__ as, const float* __restrict__ ad)
{
    int kh = blockIdx.x;
    int k = kh >> 3, h = kh & 7;
    int t = threadIdx.x;
    float wv = W[(size_t)k * HCOLS + h * FMD + t];
    float sa = wv * as[h * FMD + t];
    float sd = wv * ad[h * FMD + t];
    __shared__ float sh[8];
    int lane = t & 31, wid = t >> 5;
    #pragma unroll
    for (int o = 16; o; o >>= 1) {
        sa += __shfl_xor_sync(0xffffffffu, sa, o);
        sd += __shfl_xor_sync(0xffffffffu, sd, o);
    }
    if (lane == 0) { sh[wid] = sa; sh[4 + wid] = sd; }
    __syncthreads();
    if (t == 0) {
        g_As[k * NH + h] = sh[0] + sh[1] + sh[2] + sh[3];
        g_Ad[k * NH + h] = sh[4] + sh[5] + sh[6] + sh[7];
    }
}

// ---------------- s,d = x @ As / x @ Ad ------------------------------------
__global__ void __launch_bounds__(512) k_sd2(const float* __restrict__ Xext, int xsel) {
    const float* X = (xsel == 1) ? g_x1 : Xext;
    int n = blockIdx.x * 8 + (threadIdx.x >> 6);
    if (n >= N_NODES) return;
    int w = (threadIdx.x >> 5) & 1, lane = threadIdx.x & 31;
    const float* xr = X + (size_t)n * FMD;
    const float* Av = (w == 0) ? g_As : g_Ad;
    float part[NH] = {};
    #pragma unroll
    for (int kk = 0; kk < 4; kk++) {
        int k = lane + kk * 32;
        float xv = xr[k];
        #pragma unroll
        for (int h = 0; h < NH; h++)
            part[h] += xv * Av[k * NH + h];
    }
    #pragma unroll
    for (int h = 0; h < NH; h++) {
        float v = part[h];
        #pragma unroll
        for (int o = 16; o; o >>= 1)
            v += __shfl_xor_sync(0xffffffffu, v, o);
        part[h] = v;
    }
    if (lane == 0) {
        float* o = (w == 0) ? g_s : g_d;
        #pragma unroll
        for (int h = 0; h < NH; h++) o[n * NH + h] = part[h];
    }
}

// ---------------- fused softmax + aggregation (warp per node, plain) -------
__global__ void __launch_bounds__(128) k_attagg(const float* __restrict__ Xext, int xsel) {
    const float* X = (xsel == 1) ? g_x1 : Xext;
    int warp = threadIdx.x >> 5, lane = threadIdx.x & 31;
    int n = blockIdx.x * 4 + warp;
    if (n >= N_NODES) return;
    int e0 = g_off[n], e1 = g_off[n + 1];

    float dn = (lane < 8) ? g_d[n * NH + lane] : 0.f;

    float m = -1e30f, den = 0.f;
    if (lane < 8) {
        for (int j = e0; j < e1; j++) {
            int s = g_srcS[j];
            float v = g_s[s * NH + lane] + dn;
            v = (v > 0.f) ? v : 0.2f * v;
            float mn = fmaxf(m, v);
            den = den * __expf(m - mn) + __expf(v - mn);
            m = mn;
        }
    }
    float inv = 1.f / (den + 1e-16f);

    float4 acc[NH];
    #pragma unroll
    for (int h = 0; h < NH; h++) acc[h] = make_float4(0.f, 0.f, 0.f, 0.f);

    for (int j = e0; j < e1; j++) {
        int s = g_srcS[j];
        float al = 0.f;
        if (lane < 8) {
            float v = g_s[s * NH + lane] + dn;
            v = (v > 0.f) ? v : 0.2f * v;
            al = __expf(v - m) * inv;
        }
        float4 xv = *(const float4*)(X + (size_t)s * FMD + lane * 4);
        #pragma unroll
        for (int h = 0; h < NH; h++) {
            float a = __shfl_sync(0xffffffffu, al, h);
            acc[h].x += a * xv.x;
            acc[h].y += a * xv.y;
            acc[h].z += a * xv.z;
            acc[h].w += a * xv.w;
        }
    }
    float* yr = g_h + (size_t)n * HCOLS + lane * 4;
    #pragma unroll
    for (int h = 0; h < NH; h++)
        *(float4*)(yr + h * FMD) = acc[h];
}

// ---------------- fp16 tensor-core GEMM (m16n8k16, fp32 accumulate) --------
// C[M,Nn] = A[M,K] * B'[K,Nn]
// TBM  : 128 (P-GEMM) or 64 (Nn=128 GEMMs)
// ASEL : 0 = ext A, 1 = g_h, 2 = dual [g_x1 | g_x2] along K (stride 128 each)
// BMODE: 0 = NT (B is [Nn,K] row-major) ; 1 = W-permuted NN (Nn==128)
// MODE : 0 = plain ; 1 = +bias route circ/mir ; 2 = relu(v*0.125+bias)->g_x1/g_x2
// smem: A row-major halves [TBM][SH]; B n-major halves [BN][SH] (K contiguous).
template <int TBM, int ASEL, int BMODE, int MODE>
__global__ void __launch_bounds__(256, (TBM == 64) ? 3 : 2) gemm_tc(
    const float* __restrict__ A, const float* __restrict__ B,
    const float* __restrict__ bias, float* __restrict__ C,
    int M, int Nn, int K, int osel)
{
    constexpr int MT = TBM / 32;          // m16 tiles per warp
    __shared__ __half sA[TBM * SH];
    __shared__ __half sB[BN * SH];

    int tid  = threadIdx.x;
    int lane = tid & 31;
    int w    = tid >> 5;
    int warp_m = w & 1;
    int warp_n = w >> 1;
    int m0 = blockIdx.x * TBM, n0 = blockIdx.y * BN;

    const float* Ap = (ASEL == 1) ? g_h : A;

    float acc[MT][4][4];
    #pragma unroll
    for (int i = 0; i < MT; i++)
        #pragma unroll
        for (int j = 0; j < 4; j++)
            #pragma unroll
            for (int q = 0; q < 4; q++) acc[i][j][q] = 0.f;

    for (int kc = 0; kc < K; kc += BK) {
        // ---- stage A (fp16, row-major) ----
        #pragma unroll
        for (int p = 0; p < TBM / 32; p++) {
            int r = (tid >> 3) + p * 32;
            int q = (tid & 7) * 4;
            float4 v = make_float4(0.f, 0.f, 0.f, 0.f);
            int m = m0 + r;
            if (m < M) {
                if (ASEL == 2) {
                    int kg = kc + q;
                    const float* src = (kg < FMD)
                        ? (g_x1 + (size_t)m * FMD + kg)
                        : (g_x2 + (size_t)m * FMD + (kg - FMD));
                    v = *(const float4*)src;
                } else {
                    v = *(const float4*)(Ap + (size_t)m * K + kc + q);
                }
            }
            *(__half2*)&sA[r * SH + q]     = __floats2half2_rn(v.x, v.y);
            *(__half2*)&sA[r * SH + q + 2] = __floats2half2_rn(v.z, v.w);
        }
        // ---- stage B (fp16, n-major: K contiguous per n row) ----
        if (BMODE == 1) {
            int f = tid & 127;
            int kbase = (tid >> 7) * 16;
            #pragma unroll
            for (int kk = 0; kk < 16; kk += 2) {
                int gk0 = kc + kbase + kk;
                int gk1 = gk0 + 1;
                float v0 = B[(size_t)(gk0 & 127) * HCOLS + ((gk0 >> 7) << 7) + f];
                float v1 = B[(size_t)(gk1 & 127) * HCOLS + ((gk1 >> 7) << 7) + f];
                *(__half2*)&sB[f * SH + kbase + kk] = __floats2half2_rn(v0, v1);
            }
        } else {
            #pragma unroll
            for (int p = 0; p < 4; p++) {
                int n = (tid >> 3) + p * 32;
                int q = (tid & 7) * 4;
                float4 v = make_float4(0.f, 0.f, 0.f, 0.f);
                if (n0 + n < Nn)
                    v = *(const float4*)(B + (size_t)(n0 + n) * K + kc + q);
                *(__half2*)&sB[n * SH + q]     = __floats2half2_rn(v.x, v.y);
                *(__half2*)&sB[n * SH + q + 2] = __floats2half2_rn(v.z, v.w);
            }
        }
        __syncthreads();

        // ---- compute: 2 K16 steps per chunk ----
        #pragma unroll
        for (int k16 = 0; k16 < 2; k16++) {
            int kb = k16 * 16;
            unsigned a[MT][4], b[4][2];
            #pragma unroll
            for (int mt = 0; mt < MT; mt++) {
                int row = warp_m * (TBM / 2) + mt * 16 + (lane >> 2);
                const __half* base = &sA[row * SH + kb + 2 * (lane & 3)];
                a[mt][0] = *(const unsigned*)(base);
                a[mt][1] = *(const unsigned*)(base + 8 * SH);
                a[mt][2] = *(const unsigned*)(base + 8);
                a[mt][3] = *(const unsigned*)(base + 8 * SH + 8);
            }
            #pragma unroll
            for (int nt = 0; nt < 4; nt++) {
                int n = warp_n * 32 + nt * 8 + (lane >> 2);
                const __half* bb = &sB[n * SH + kb + 2 * (lane & 3)];
                b[nt][0] = *(const unsigned*)(bb);
                b[nt][1] = *(const unsigned*)(bb + 8);
            }
            #pragma unroll
            for (int mt = 0; mt < MT; mt++)
                #pragma unroll
                for (int nt = 0; nt < 4; nt++)
                    mma_f16(acc[mt][nt], a[mt], b[nt]);
        }
        __syncthreads();
    }

    // ---- epilogue (fragment layout identical to m16n8k8) ----
    #pragma unroll
    for (int mt = 0; mt < MT; mt++) {
        int rg = m0 + warp_m * (TBM / 2) + mt * 16 + (lane >> 2);
        #pragma unroll
        for (int nt = 0; nt < 4; nt++) {
            int colg = n0 + warp_n * 32 + nt * 8 + (lane & 3) * 2;
            const float* dv = acc[mt][nt];
            #pragma unroll
            for (int half = 0; half < 2; half++) {
                int m = rg + half * 8;
                if (m >= M) continue;
                float v0 = dv[half * 2 + 0];
                float v1 = dv[half * 2 + 1];
                if (MODE == 0) {
                    if (colg + 1 < Nn) {
                        *(float2*)(C + (size_t)m * Nn + colg) = make_float2(v0, v1);
                    } else if (colg < Nn) {
                        C[(size_t)m * Nn + colg] = v0;
                    }
                } else if (MODE == 1) {
                    v0 += bias[colg];
                    v1 += bias[colg + 1];
                    float* base = (m < CIRCN)
                        ? (C + PQ + (size_t)m * OCD)
                        : (C + PQ + (size_t)CIRCN * OCD + (size_t)(m - CIRCN) * OCD);
                    *(float2*)(base + colg) = make_float2(v0, v1);
                } else {
                    v0 = fmaxf(v0 * 0.125f + bias[colg], 0.f);
                    v1 = fmaxf(v1 * 0.125f + bias[colg + 1], 0.f);
                    float* o = (osel == 1) ? g_x1 : g_x2;
                    *(float2*)(o + (size_t)m * FMD + colg) = make_float2(v0, v1);
                }
            }
        }
    }
}

// ---------------- launch ---------------------------------------------------
extern "C" void kernel_launch(void* const* d_in, const int* in_sizes, int n_in,
                              void* d_out, int out_size)
{
    const float* x   = (const float*)d_in[0];
    const void*  ei  = d_in[1];
    const float* W1  = (const float*)d_in[2];
    const float* as1 = (const float*)d_in[3];
    const float* ad1 = (const float*)d_in[4];
    const float* b1  = (const float*)d_in[5];
    const float* W2  = (const float*)d_in[6];
    const float* as2 = (const float*)d_in[7];
    const float* ad2 = (const float*)d_in[8];
    const float* b2  = (const float*)d_in[9];
    const float* Wc  = (const float*)d_in[10];
    const float* bc  = (const float*)d_in[11];
    float* out = (float*)d_out;

    dim3 gOut64((N_NODES + 63) / 64, 1);     // 313 CTAs
    int gAtt = (N_NODES + 3) / 4;
    int gSd  = (N_NODES + 7) / 8;

    // ---- fork: attention-prep chain on side stream s1 ----
    cudaEventRecord(g_evF, 0);
    cudaStreamWaitEvent(g_s1, g_evF, 0);
    k_fold<<<HCOLS, 128, 0, g_s1>>>(W1, as1, ad1);
    k_sd2<<<gSd, 512, 0, g_s1>>>(x, 0);
    k_fold<<<HCOLS, 128, 0, g_s1>>>(W2, as2, ad2);   // sd2_1 done reading As/Ad
    cudaEventRecord(g_evJ, g_s1);

    // ---- main stream: CSR build ----
    k_init<<<(N_NODES + 255) / 256, 256>>>((const int*)ei);
    k_decode<<<(ETOT + 255) / 256, 256>>>(ei);
    k_scan1<<<SCAN_BLK, 1024>>>();
    k_scan3<<<SCAN_BLK, 1024>>>();
    k_scatter<<<(ETOT + 255) / 256, 256>>>();

    // ---- join: attagg needs CSR + (fold1, sd2_1); sd2_2 needs fold2 ----
    cudaStreamWaitEvent(0, g_evJ, 0);

    // ---- layer 1 ----
    k_attagg<<<gAtt, 128>>>(x, 0);
    gemm_tc<64, 1, 1, 2><<<gOut64, 256>>>(nullptr, W1, b1, nullptr,
                                          N_NODES, FMD, HCOLS, 1);

    // ---- layer 2 ----
    k_sd2<<<gSd, 512>>>(nullptr, 1);
    k_attagg<<<gAtt, 128>>>(nullptr, 1);
    gemm_tc<64, 1, 1, 2><<<gOut64, 256>>>(nullptr, W2, b2, nullptr,
                                          N_NODES, FMD, HCOLS, 2);

    // ---- classifier ----
    gemm_tc<64, 2, 0, 1><<<gOut64, 256>>>(nullptr, Wc, bc, out,
                                          N_NODES, OCD, 2 * FMD, 0);

    // ---- P = circ @ mir^T ----
    const float* circ = out + PQ;
    const float* mir  = out + PQ + (size_t)CIRCN * OCD;
    dim3 gP((CIRCN + 127) / 128, (MIRN + BN - 1) / BN);
    gemm_tc<128, 0, 0, 0><<<gP, 256>>>(circ, mir, nullptr, out,
                                       CIRCN, MIRN, FMD, 0);
}